// round 15
// baseline (speedup 1.0000x reference)
#include <cuda_runtime.h>

// Problem constants: B=2048, F=P*N=4096, C=10
#define F        4096
#define C        10

// wprep geometry: 80 blocks = (c, seg)
#define WSEG     8
#define WPREP_T  256
#define WF       (F / WSEG)
#define NWARP    (WPREP_T / 32)

// lse geometry
#define TX       128                   // threads over f
#define TY       4                     // row groups
#define LTHREADS (TX * TY)             // 512
#define RG       4                     // rows per thread
#define ROWS     (TY * RG)             // 16 rows per block -> grid 128
#define FT       256                   // f per tile
#define NT       (F / FT)              // 16 tiles
#define NSLOT    4                     // ring depth
#define FPT      (FT / TX)             // 2 f per thread per tile
#define XS_FLOATS (ROWS * FT)          // 4096 floats = 16KB per slot
#define XS_BYTES  (XS_FLOATS * 4)
#define ROW_BYTES (FT * 4)             // 1KB per row per tile
#define SMEM_FLOATS (C * F + NSLOT * XS_FLOATS)
#define SMEM_BYTES  (SMEM_FLOATS * 4)  // 163840 + 65536 = 229376 B

__device__ float g_pt[C * F];          // pt[c*F + f] = exp(weight[c,f])
__device__ float g_ps[C * WSEG];       // segment partial sums of exp(weight[c,:])

// ---------- packed f32x2 helpers ----------
__device__ __forceinline__ unsigned long long pack2(float lo, float hi) {
    unsigned long long r;
    asm("mov.b64 %0, {%1, %2};" : "=l"(r) : "f"(lo), "f"(hi));
    return r;
}
__device__ __forceinline__ void unpack2(unsigned long long v, float& lo, float& hi) {
    asm("mov.b64 {%0, %1}, %2;" : "=f"(lo), "=f"(hi) : "l"(v));
}
__device__ __forceinline__ unsigned long long fma2(unsigned long long a,
                                                   unsigned long long b,
                                                   unsigned long long c) {
    unsigned long long d;
    asm("fma.rn.f32x2 %0, %1, %2, %3;" : "=l"(d) : "l"(a), "l"(b), "l"(c));
    return d;
}
// ---------- mbarrier / bulk-copy helpers ----------
__device__ __forceinline__ unsigned int smem_u32(const void* p) {
    return (unsigned int)__cvta_generic_to_shared(p);
}
__device__ __forceinline__ void mbar_init(unsigned int a, unsigned int cnt) {
    asm volatile("mbarrier.init.shared.b64 [%0], %1;" :: "r"(a), "r"(cnt) : "memory");
}
__device__ __forceinline__ void mbar_expect_tx(unsigned int a, unsigned int bytes) {
    asm volatile("mbarrier.arrive.expect_tx.shared.b64 _, [%0], %1;"
                 :: "r"(a), "r"(bytes) : "memory");
}
__device__ __forceinline__ void mbar_wait(unsigned int a, unsigned int parity) {
    asm volatile(
        "{\n\t.reg .pred P;\n\t"
        "WL_%=:\n\t"
        "mbarrier.try_wait.parity.shared.b64 P, [%0], %1, 0x989680;\n\t"
        "@P bra.uni WD_%=;\n\t"
        "bra.uni WL_%=;\n\t"
        "WD_%=:\n\t}"
        :: "r"(a), "r"(parity) : "memory");
}
__device__ __forceinline__ void bulk_g2s(unsigned int dst, const void* src,
                                         unsigned int bytes, unsigned int mbar) {
    asm volatile(
        "cp.async.bulk.shared::cta.global.mbarrier::complete_tx::bytes "
        "[%0], [%1], %2, [%3];"
        :: "r"(dst), "l"(src), "r"(bytes), "r"(mbar) : "memory");
}

// Kernel 1: exp(weight) + segment partial sums.
__global__ void wprep_kernel(const float* __restrict__ w) {
    const int c   = blockIdx.x >> 3;
    const int seg = blockIdx.x & 7;
    const int tid = threadIdx.x;
    const int f   = seg * WF + tid * 2;

    const float2 wv = *reinterpret_cast<const float2*>(w + (size_t)c * F + f);
    const float e0 = __expf(wv.x), e1 = __expf(wv.y);
    *reinterpret_cast<float2*>(g_pt + (size_t)c * F + f) = make_float2(e0, e1);

    float sum = e0 + e1;
    __shared__ float sred[NWARP];
    #pragma unroll
    for (int o = 16; o > 0; o >>= 1) sum += __shfl_xor_sync(0xffffffffu, sum, o);
    if ((tid & 31) == 0) sred[tid >> 5] = sum;
    __syncthreads();
    if (tid == 0) {
        float t = 0.f;
        #pragma unroll
        for (int i = 0; i < NWARP; i++) t += sred[i];
        g_ps[c * WSEG + seg] = t;
    }
}

// Kernel 2: pt smem-resident; x streamed via a 4-deep cp.async.bulk ring.
// 512 threads (tx=128, ty=4), RG=4 rows/thread, f-packed f32x2 inner product.
__global__ __launch_bounds__(LTHREADS, 1) void lse_kernel(const float* __restrict__ x,
                                                          float* __restrict__ out) {
    extern __shared__ float s[];
    float* s_pt = s;                     // C*F floats (160KB)
    float* s_x  = s + C * F;             // NSLOT x 4096 floats (64KB)
    __shared__ __align__(8) unsigned long long mbar_store[NSLOT];

    const int tid = threadIdx.x;
    const int tx  = tid & (TX - 1);
    const int ty  = tid >> 7;
    const int bb  = blockIdx.x * ROWS;

    unsigned int mb[NSLOT], sx[NSLOT];
    #pragma unroll
    for (int sI = 0; sI < NSLOT; sI++) {
        mb[sI] = smem_u32(&mbar_store[sI]);
        sx[sI] = smem_u32(s_x + sI * XS_FLOATS);
    }

    // Stage pt once: 10240 float4 over 512 threads, coalesced.
    {
        float4* s4 = reinterpret_cast<float4*>(s_pt);
        const float4* g4 = reinterpret_cast<const float4*>(g_pt);
        #pragma unroll
        for (int k = 0; k < (C * F / 4) / LTHREADS; k++)
            s4[tid + k * LTHREADS] = g4[tid + k * LTHREADS];
    }
    if (tid == 0) {
        #pragma unroll
        for (int sI = 0; sI < NSLOT; sI++) mbar_init(mb[sI], 1);
    }
    __syncthreads();   // pt visible + mbarriers initialized

    // Prologue: issue tiles 0..2 (3 in flight).
    if (tid == 0) {
        #pragma unroll
        for (int t = 0; t < NSLOT - 1; t++) {
            mbar_expect_tx(mb[t], XS_BYTES);
            #pragma unroll
            for (int r = 0; r < ROWS; r++)
                bulk_g2s(sx[t] + r * ROW_BYTES,
                         x + (size_t)(bb + r) * F + t * FT, ROW_BYTES, mb[t]);
        }
    }

    unsigned long long acc2[RG][C];
    #pragma unroll
    for (int r = 0; r < RG; r++)
        #pragma unroll
        for (int c = 0; c < C; c++) acc2[r][c] = 0ull;

    for (int t = 0; t < NT; t++) {
        const int slot = t & (NSLOT - 1);
        mbar_wait(mb[slot], (t >> 2) & 1);
        __syncthreads();   // all threads done with tile t-1's slot; tile t visible

        // Issue tile t+3 into the slot consumed at t-1 (safe past this sync).
        if (tid == 0 && t + NSLOT - 1 < NT) {
            const int nt = t + NSLOT - 1;
            const int ns = nt & (NSLOT - 1);
            mbar_expect_tx(mb[ns], XS_BYTES);
            #pragma unroll
            for (int r = 0; r < ROWS; r++)
                bulk_g2s(sx[ns] + r * ROW_BYTES,
                         x + (size_t)(bb + r) * F + nt * FT, ROW_BYTES, mb[ns]);
        }

        // Compute tile t: x + pt both from smem.
        const float* xs = s_x + slot * XS_FLOATS + (ty * RG) * FT + tx * FPT;
        unsigned long long e[RG];
        #pragma unroll
        for (int r = 0; r < RG; r++) {
            const float2 xv = *reinterpret_cast<const float2*>(xs + r * FT);
            e[r] = pack2(__expf(xv.x), __expf(xv.y));
        }
        const float* pbase = s_pt + t * FT + tx * FPT;
        #pragma unroll
        for (int c = 0; c < C; c++) {
            const unsigned long long pv =
                *reinterpret_cast<const unsigned long long*>(pbase + c * F);
            #pragma unroll
            for (int r = 0; r < RG; r++)
                acc2[r][c] = fma2(e[r], pv, acc2[r][c]);
        }
    }

    // Reduction: reuse x slots as scratch.
    __syncthreads();
    float* s_red = s_x;                  // 16 warps x (RG*C)

    #pragma unroll
    for (int r = 0; r < RG; r++)
        #pragma unroll
        for (int c = 0; c < C; c++) {
            float lo, hi;
            unpack2(acc2[r][c], lo, hi);
            float v = lo + hi;
            #pragma unroll
            for (int o = 16; o > 0; o >>= 1) v += __shfl_xor_sync(0xffffffffu, v, o);
            if ((tid & 31) == 0) s_red[(tid >> 5) * (RG * C) + r * C + c] = v;
        }
    __syncthreads();

    if (tid < ROWS * C) {                // 160 threads
        const int row = tid / C, c = tid % C;
        const int tyo = row / RG, r = row % RG;
        float sm = 0.f;
        #pragma unroll
        for (int wi = 0; wi < TX / 32; wi++)
            sm += s_red[(tyo * (TX / 32) + wi) * (RG * C) + r * C + c];
        float z = 0.f;
        #pragma unroll
        for (int k = 0; k < WSEG; k++) z += g_ps[c * WSEG + k];
        out[(size_t)(bb + row) * C + c] = logf(sm) - logf(z);
    }
}

extern "C" void kernel_launch(void* const* d_in, const int* in_sizes, int n_in,
                              void* d_out, int out_size) {
    const float* x = (const float*)d_in[0];   // (2048, 64, 64) fp32
    const float* w = (const float*)d_in[1];   // (10, 4096) fp32
    float* out = (float*)d_out;               // (2048, 10) fp32

    const int B = in_sizes[0] / F;            // 2048

    cudaFuncSetAttribute(lse_kernel, cudaFuncAttributeMaxDynamicSharedMemorySize,
                         SMEM_BYTES);

    wprep_kernel<<<C * WSEG, WPREP_T>>>(w);
    lse_kernel<<<B / ROWS, LTHREADS, SMEM_BYTES>>>(x, out);
}

// round 17
// speedup vs baseline: 1.4858x; 1.4858x over previous
#include <cuda_runtime.h>
#include <cuda_bf16.h>
#include <cstdint>

// Problem: B=2048, F=4096, C=10.  out[b,c] = log(sum_f exp(x)*exp(w)) - log z
#define F        4096
#define C        10
#define BROWS    2048

// GEMM geometry: mma.sync m16n8k16 bf16, N padded to 16 (cols 10..15 zero).
#define NSPLIT   16                    // K splits
#define KS       (F / NSPLIT)          // 256 K per split
#define NKT_G    (F / 16)              // 256 global k-tiles
#define MT       128                   // rows per CTA
#define MMA_T    256                   // 8 warps; warp owns 16 rows

// wsum geometry
#define WSEG     8
#define WPREP_T  256
#define NWARP    (WPREP_T / 32)
#define WF       (F / WSEG)

__device__ uint32_t g_bfrag[NKT_G * 128];      // [ktile][half][lane][reg] bf16x2
__device__ float    g_ps[C * WSEG];            // segment sums of exp(w)
__device__ float    g_part[NSPLIT * BROWS * C];// split-K partials

// ---------- helpers ----------
__device__ __forceinline__ uint32_t cvt_bf2(float hi, float lo) {
    uint32_t r;
    asm("cvt.rn.bf16x2.f32 %0, %1, %2;" : "=r"(r) : "f"(hi), "f"(lo));
    return r;
}
__device__ __forceinline__ void mma16816(float* c, uint32_t a0, uint32_t a1,
                                         uint32_t a2, uint32_t a3,
                                         uint32_t b0, uint32_t b1) {
    asm volatile(
        "mma.sync.aligned.m16n8k16.row.col.f32.bf16.bf16.f32 "
        "{%0,%1,%2,%3}, {%4,%5,%6,%7}, {%8,%9}, {%0,%1,%2,%3};"
        : "+f"(c[0]), "+f"(c[1]), "+f"(c[2]), "+f"(c[3])
        : "r"(a0), "r"(a1), "r"(a2), "r"(a3), "r"(b0), "r"(b1));
}

// ---------------- Kernel 1: fragment-ordered bf16 exp(weight) table ----------------
// For ktile kt, n-half h, lane l, reg r: n = 8h + l/4, k = kt*16 + (l%4)*2 + r*8.
// Stored at idx = kt*128 + h*64 + l*2 + r. Rows n >= 10 are zero padding.
__global__ void bfrag_kernel(const float* __restrict__ w) {
    const int idx = blockIdx.x * 256 + threadIdx.x;   // 0..32767
    const int r  = idx & 1;
    const int l  = (idx >> 1) & 31;
    const int h  = (idx >> 6) & 1;
    const int kt = idx >> 7;
    const int n  = 8 * h + (l >> 2);
    const int k  = kt * 16 + (l & 3) * 2 + r * 8;
    uint32_t v = 0u;
    if (n < C) {
        const float e0 = __expf(w[n * F + k]);
        const float e1 = __expf(w[n * F + k + 1]);
        v = cvt_bf2(e1, e0);                          // lo = e(k), hi = e(k+1)
    }
    g_bfrag[idx] = v;
}

// ---------------- Kernel 2: z segment sums ----------------
__global__ void wsum_kernel(const float* __restrict__ w) {
    const int c   = blockIdx.x >> 3;
    const int seg = blockIdx.x & 7;
    const int tid = threadIdx.x;
    const int f   = seg * WF + tid * 2;

    const float2 wv = *reinterpret_cast<const float2*>(w + (size_t)c * F + f);
    float sum = __expf(wv.x) + __expf(wv.y);
    __shared__ float sred[NWARP];
    #pragma unroll
    for (int o = 16; o > 0; o >>= 1) sum += __shfl_xor_sync(0xffffffffu, sum, o);
    if ((tid & 31) == 0) sred[tid >> 5] = sum;
    __syncthreads();
    if (tid == 0) {
        float t = 0.f;
        #pragma unroll
        for (int i = 0; i < NWARP; i++) t += sred[i];
        g_ps[c * WSEG + seg] = t;
    }
}

// ---------------- Kernel 3: exp(x) @ expW^T via HMMA, split-K ----------------
// 256 CTAs = 16 M-tiles x 16 K-splits; 256 threads; warp owns 16 rows x KS.
// No smem: A loaded fragment-direct from gmem (exp+cvt in regs), B from g_bfrag.
__global__ __launch_bounds__(MMA_T) void mma_kernel(const float* __restrict__ x) {
    const int tid   = threadIdx.x;
    const int wid   = tid >> 5;
    const int lane  = tid & 31;
    const int mtile = blockIdx.x / NSPLIT;
    const int split = blockIdx.x % NSPLIT;

    const int row0 = mtile * MT + wid * 16 + (lane >> 2);
    const int kcol = (lane & 3) * 2;

    const float* xr0 = x + (size_t)row0 * F + split * KS + kcol;
    const float* xr1 = xr0 + 8 * F;

    float c0[4] = {0.f, 0.f, 0.f, 0.f};
    float c1[4] = {0.f, 0.f, 0.f, 0.f};

    #pragma unroll 4
    for (int kt = 0; kt < KS / 16; kt++) {
        const int ko  = kt * 16;
        const int ktg = split * (KS / 16) + kt;

        // A fragment source: rows {row0, row0+8} x k {+0, +8}, float2 each.
        const float2 xa = *reinterpret_cast<const float2*>(xr0 + ko);
        const float2 xb = *reinterpret_cast<const float2*>(xr1 + ko);
        const float2 xc = *reinterpret_cast<const float2*>(xr0 + ko + 8);
        const float2 xd = *reinterpret_cast<const float2*>(xr1 + ko + 8);

        // B fragments: coalesced LDG.64 from the L2-resident table.
        const uint2 bh0 = *reinterpret_cast<const uint2*>(g_bfrag + ktg * 128 + lane * 2);
        const uint2 bh1 = *reinterpret_cast<const uint2*>(g_bfrag + ktg * 128 + 64 + lane * 2);

        const uint32_t a0 = cvt_bf2(__expf(xa.y), __expf(xa.x));
        const uint32_t a1 = cvt_bf2(__expf(xb.y), __expf(xb.x));
        const uint32_t a2 = cvt_bf2(__expf(xc.y), __expf(xc.x));
        const uint32_t a3 = cvt_bf2(__expf(xd.y), __expf(xd.x));

        mma16816(c0, a0, a1, a2, a3, bh0.x, bh0.y);   // n 0..7
        mma16816(c1, a0, a1, a2, a3, bh1.x, bh1.y);   // n 8..15 (10..15 zero)
    }

    // Epilogue: D fragment -> g_part[split][row][n], n < 10 only.
    float* p = g_part + ((size_t)split * BROWS + row0) * C;
    p[kcol]         = c0[0];
    p[kcol + 1]     = c0[1];
    p[8 * C + kcol]     = c0[2];
    p[8 * C + kcol + 1] = c0[3];
    if ((lane & 3) == 0) {
        p[8] = c1[0];
        p[9] = c1[1];
        p[8 * C + 8] = c1[2];
        p[8 * C + 9] = c1[3];
    }
}

// ---------------- Kernel 4: combine split-K partials + logs ----------------
__global__ void combine_kernel(float* __restrict__ out) {
    const int i = blockIdx.x * 512 + threadIdx.x;   // 20480 outputs
    const int c = i % C;
    float sm = 0.f;
    #pragma unroll
    for (int s = 0; s < NSPLIT; s++)
        sm += g_part[(size_t)s * BROWS * C + i];
    float z = 0.f;
    #pragma unroll
    for (int k = 0; k < WSEG; k++) z += g_ps[c * WSEG + k];
    out[i] = logf(sm) - logf(z);
}

extern "C" void kernel_launch(void* const* d_in, const int* in_sizes, int n_in,
                              void* d_out, int out_size) {
    const float* x = (const float*)d_in[0];   // (2048, 64, 64) fp32
    const float* w = (const float*)d_in[1];   // (10, 4096) fp32
    float* out = (float*)d_out;               // (2048, 10) fp32

    bfrag_kernel<<<128, 256>>>(w);
    wsum_kernel<<<C * WSEG, WPREP_T>>>(w);
    mma_kernel<<<(BROWS / MT) * NSPLIT, MMA_T>>>(x);
    combine_kernel<<<(BROWS * C) / 512, 512>>>(out);
}